// round 9
// baseline (speedup 1.0000x reference)
#include <cuda_runtime.h>
#include <cuda_fp16.h>
#include <cstdint>

// CapsuleConv = GEMM (rows=(b,w,a)=130944, K=(k,n,x)=384, cols=(m,d)=128) + fused LayerNorm.
// Persistent-CTA fp16 mma.sync: 128 CTAs x 512 threads, 8 tiles each.
// B (all 3 k-slices) resident in smem for the whole kernel; per tile only an
// inline A build + one long 24-step mma run + fused LN epilogue.

#define BB    16
#define NIN   32
#define LLEN  2048
#define MMO   32
#define WOUTN 2046

#define THREADS 512
#define WTILE   32          // w per tile (M = 128 output rows)
#define ASTRIDE 272         // smem row stride bytes (128 fp16 = 256B + 16 pad)
#define A_ROWS  136         // (WTILE + 2) * 4
#define A_MAT   (A_ROWS * ASTRIDE)        // 36992
#define B_MAT   (128 * ASTRIDE)           // 34816
#define SSTRIDE 132                       // epilogue fp32 row stride (floats)
#define S_BYTES (128 * SSTRIDE * 4)       // 67584
#define OFF_B   S_BYTES                   // B after max(A, S) region
#define SMEM_BYTES (OFF_B + 3 * B_MAT)    // 172032
#define OUT_SCALE (1.0f / 32.0f)

// ---- persistent scratch: rearranged fp16 weight ----
__device__ __half g_B[3 * 128 * 128];     // B[k][c=m*4+d][n*4+x] = w (unscaled)

// ======================= helpers =======================
__device__ __forceinline__ uint32_t smem_u32(const void* p) {
    uint32_t a;
    asm("{ .reg .u64 t; cvta.to.shared.u64 t, %1; cvt.u32.u64 %0, t; }" : "=r"(a) : "l"(p));
    return a;
}
__device__ __forceinline__ void cp16(uint32_t dst, const void* src) {
    asm volatile("cp.async.cg.shared.global [%0], [%1], 16;" :: "r"(dst), "l"(src));
}
__device__ __forceinline__ void cp_commit() {
    asm volatile("cp.async.commit_group;" ::: "memory");
}
__device__ __forceinline__ void ldsm4(uint32_t* r, uint32_t addr) {
    asm volatile("ldmatrix.sync.aligned.m8n8.x4.shared.b16 {%0,%1,%2,%3}, [%4];"
                 : "=r"(r[0]), "=r"(r[1]), "=r"(r[2]), "=r"(r[3]) : "r"(addr));
}
__device__ __forceinline__ void mma16816(float* d, const uint32_t* a,
                                         uint32_t b0, uint32_t b1) {
    asm volatile(
        "mma.sync.aligned.m16n8k16.row.col.f32.f16.f16.f32 "
        "{%0,%1,%2,%3}, {%4,%5,%6,%7}, {%8,%9}, {%0,%1,%2,%3};"
        : "+f"(d[0]), "+f"(d[1]), "+f"(d[2]), "+f"(d[3])
        : "r"(a[0]), "r"(a[1]), "r"(a[2]), "r"(a[3]), "r"(b0), "r"(b1));
}
__device__ __forceinline__ uint32_t pkh(__half a, __half b) {
    __half2 t(a, b);
    return *reinterpret_cast<uint32_t*>(&t);
}

// ======================= tiny prepass: rearrange + convert weight =======================
__global__ __launch_bounds__(256)
void prep_b(const float* __restrict__ w) {
    const int idx = blockIdx.x * 256 + threadIdx.x;   // < 49152
    const int col = idx & 127;       // n*4+x
    const int row = idx >> 7;
    const int c = row & 127;         // m*4+d
    const int k = row >> 7;
    const int n = col >> 2, xx = col & 3;
    const int m = c >> 2, d = c & 3;
    g_B[idx] = __float2half_rn(w[(((k * NIN + n) * 4 + xx) * 4 + d) * MMO + m]);
}

// ======================= main persistent kernel =======================
__global__ __launch_bounds__(THREADS, 1)
void caps_mma_kernel(const float* __restrict__ x,
                     const float* __restrict__ gamma,
                     const float* __restrict__ beta,
                     float* __restrict__ out) {
    extern __shared__ char dsm[];
    const uint32_t smem = smem_u32(dsm);

    const int tid = threadIdx.x;
    const int wid = tid >> 5, lid = tid & 31;
    const int wm = wid & 3;           // rows wm*32 .. +32
    const int wn = wid >> 2;          // cols wn*32 .. +32
    const uint32_t lane_off = (uint32_t)((lid & 15) * ASTRIDE + (lid >> 4) * 16);

    // ---- load ALL of B once: 6144 cp16, 12/thread ----
#pragma unroll
    for (int j = 0; j < 12; ++j) {
        const int u = tid + THREADS * j;          // < 6144
        const int slice = u >> 11;                // k
        const int row = (u >> 4) & 127;
        const int seg = u & 15;
        cp16(smem + OFF_B + (uint32_t)(slice * B_MAT + row * ASTRIDE + seg * 16),
             g_B + ((size_t)slice * 128 + row) * 128 + seg * 8);
    }
    cp_commit();

    float gam[16], bet[16];
#pragma unroll
    for (int i = 0; i < 16; i++) { gam[i] = __ldg(gamma + i); bet[i] = __ldg(beta + i); }

    for (int t = 0; t < 8; ++t) {
        const int tile = blockIdx.x + 128 * t;    // 0..1023
        const int b  = tile >> 6;
        const int w0 = (tile & 63) * WTILE;
        const float* xb = x + (size_t)b * NIN * LLEN * 16;

        // ---- build A tile inline: LDG fp32 -> f2h -> STS ----
        // Part 1: ll in [0,32): no clamp (w0+31 <= 2047).
#pragma unroll
        for (int j = 0; j < 8; ++j) {
            const int F  = tid + THREADS * j;     // < 4096
            const int a  = F & 3;
            const int ll = (F >> 2) & 31;
            const int nl = F >> 7;
            const float4 v = *reinterpret_cast<const float4*>(
                xb + ((size_t)nl * LLEN + (w0 + ll)) * 16 + a * 4);
            *reinterpret_cast<uint2*>(dsm + (uint32_t)((ll * 4 + a) * ASTRIDE + nl * 8)) =
                make_uint2(pkh(__float2half_rn(v.x), __float2half_rn(v.y)),
                           pkh(__float2half_rn(v.z), __float2half_rn(v.w)));
        }
        // Part 2: ll in {32,33} (overhang; clamp; garbage only for w>=WOUT, never stored)
        if (tid < 256) {
            const int a  = tid & 3;
            const int ll = 32 + ((tid >> 2) & 1);
            const int nl = tid >> 3;
            int l = w0 + ll; if (l > LLEN - 1) l = LLEN - 1;
            const float4 v = *reinterpret_cast<const float4*>(
                xb + ((size_t)nl * LLEN + l) * 16 + a * 4);
            *reinterpret_cast<uint2*>(dsm + (uint32_t)((ll * 4 + a) * ASTRIDE + nl * 8)) =
                make_uint2(pkh(__float2half_rn(v.x), __float2half_rn(v.y)),
                           pkh(__float2half_rn(v.z), __float2half_rn(v.w)));
        }
        if (t == 0) asm volatile("cp.async.wait_group 0;" ::: "memory");   // B resident
        __syncthreads();   // A visible (t==0: B too)

        float d[2][4][4];
#pragma unroll
        for (int i = 0; i < 2; i++)
#pragma unroll
            for (int j = 0; j < 4; j++)
#pragma unroll
                for (int q = 0; q < 4; q++) d[i][j][q] = 0.0f;

        // ---- 3 k-passes, no syncs in between (A, B read-only) ----
#pragma unroll
        for (int k = 0; k < 3; ++k) {
            const uint32_t sA = smem + (uint32_t)((wm * 32 + 4 * k) * ASTRIDE) + lane_off;
            const uint32_t sB = smem + OFF_B + (uint32_t)(k * B_MAT)
                              + (uint32_t)(wn * 32 * ASTRIDE) + lane_off;
#pragma unroll
            for (int ks = 0; ks < 8; ++ks) {
                const uint32_t kb = ks * 32;   // k16 step = 32 bytes
                uint32_t Ar[2][4], Br[2][4];
#pragma unroll
                for (int mf = 0; mf < 2; ++mf)
                    ldsm4(Ar[mf], sA + (uint32_t)(mf * 16) * ASTRIDE + kb);
#pragma unroll
                for (int bg = 0; bg < 2; ++bg)
                    ldsm4(Br[bg], sB + (uint32_t)(bg * 16) * ASTRIDE + kb);
#pragma unroll
                for (int mf = 0; mf < 2; ++mf)
#pragma unroll
                    for (int bg = 0; bg < 2; ++bg) {
                        mma16816(d[mf][bg * 2],     Ar[mf], Br[bg][0], Br[bg][2]);
                        mma16816(d[mf][bg * 2 + 1], Ar[mf], Br[bg][1], Br[bg][3]);
                    }
            }
        }

        // ---- epilogue: accum -> smem (overwrites A region), fused LayerNorm ----
        __syncthreads();   // all A reads done before S overwrite
        float* S = reinterpret_cast<float*>(dsm);   // [128][SSTRIDE]
        const int g = lid >> 2, t4 = lid & 3;
#pragma unroll
        for (int mf = 0; mf < 2; ++mf)
#pragma unroll
            for (int ng = 0; ng < 4; ++ng) {
                const int r = wm * 32 + mf * 16 + g;
                const int c = wn * 32 + ng * 8 + t4 * 2;
                S[r * SSTRIDE + c]           = d[mf][ng][0];
                S[r * SSTRIDE + c + 1]       = d[mf][ng][1];
                S[(r + 8) * SSTRIDE + c]     = d[mf][ng][2];
                S[(r + 8) * SSTRIDE + c + 1] = d[mf][ng][3];
            }
        __syncthreads();

        // 1024 LN groups (wl 0..31 x m 0..31), 2 per thread
#pragma unroll
        for (int gq = 0; gq < 2; ++gq) {
            const int G  = tid + gq * THREADS;
            const int wl = G >> 5;
            const int m  = G & 31;
            const int w  = w0 + wl;
            if (w >= WOUTN) continue;

            float vals[16];
#pragma unroll
            for (int a = 0; a < 4; a++) {
                const float4 v = *reinterpret_cast<const float4*>(
                    S + (wl * 4 + a) * SSTRIDE + m * 4);
                vals[a * 4 + 0] = v.x * OUT_SCALE; vals[a * 4 + 1] = v.y * OUT_SCALE;
                vals[a * 4 + 2] = v.z * OUT_SCALE; vals[a * 4 + 3] = v.w * OUT_SCALE;
            }
            float mu = 0.0f;
#pragma unroll
            for (int i = 0; i < 16; i++) mu += vals[i];
            mu *= 0.0625f;
            float var = 0.0f;
#pragma unroll
            for (int i = 0; i < 16; i++) {
                const float dv = vals[i] - mu;
                var = fmaf(dv, dv, var);
            }
            var *= 0.0625f;
            const float inv = rsqrtf(var + 1e-5f);

            const size_t base = (((size_t)b * MMO + m) * WOUTN + w) * 16;
#pragma unroll
            for (int q = 0; q < 4; q++) {
                float4 o;
                o.x = fmaf((vals[q * 4 + 0] - mu) * inv, gam[q * 4 + 0], bet[q * 4 + 0]);
                o.y = fmaf((vals[q * 4 + 1] - mu) * inv, gam[q * 4 + 1], bet[q * 4 + 1]);
                o.z = fmaf((vals[q * 4 + 2] - mu) * inv, gam[q * 4 + 2], bet[q * 4 + 2]);
                o.w = fmaf((vals[q * 4 + 3] - mu) * inv, gam[q * 4 + 3], bet[q * 4 + 3]);
                *reinterpret_cast<float4*>(out + base + q * 4) = o;
            }
        }
        __syncthreads();   // S reads done before next tile's A build
    }
}

extern "C" void kernel_launch(void* const* d_in, const int* in_sizes, int n_in,
                              void* d_out, int out_size) {
    const float* x     = (const float*)d_in[0];
    const float* w     = (const float*)d_in[1];
    const float* gamma = (const float*)d_in[2];
    const float* beta  = (const float*)d_in[3];
    float* out = (float*)d_out;

    prep_b<<<192, 256>>>(w);

    cudaFuncSetAttribute(caps_mma_kernel,
                         cudaFuncAttributeMaxDynamicSharedMemorySize, SMEM_BYTES);
    caps_mma_kernel<<<128, THREADS, SMEM_BYTES>>>(x, gamma, beta, out);
}

// round 10
// speedup vs baseline: 1.1002x; 1.1002x over previous
#include <cuda_runtime.h>
#include <cuda_fp16.h>
#include <cstdint>

// CapsuleConv = GEMM (rows=(b,w,a)=130944, K=(k,n,x)=384, cols=(m,d)=128) + fused LayerNorm.
// Single-pass fp16 mma.sync. 128 threads/CTA, 2x2 warp grid of 64x64 warp tiles
// (halves smem operand duplication, 32 independent MMAs per ks-iter per warp).
// A tile built inline (fp32 LDG -> f2h -> STS); B ping-pong via cp.async. 2 CTAs/SM.

#define BB    16
#define NIN   32
#define LLEN  2048
#define MMO   32
#define WOUTN 2046

#define THREADS 128
#define WTILE   32          // w per CTA (M = 128 output rows)
#define ASTRIDE 272         // smem row stride bytes (128 fp16 = 256B + 16 pad)
#define A_ROWS  136         // (WTILE + 2) * 4
#define A_MAT   (A_ROWS * ASTRIDE)        // 36992
#define B_MAT   (128 * ASTRIDE)           // 34816
#define OFF_B   A_MAT
#define SMEM_BYTES (A_MAT + 2 * B_MAT)    // 106624 -> 2 CTAs/SM
#define SSTRIDE 132         // epilogue fp32 row stride (floats)
#define OUT_SCALE (1.0f / 32.0f)

// ---- persistent scratch: rearranged fp16 weight ----
__device__ __half g_B[3 * 128 * 128];     // B[k][c=m*4+d][n*4+x] = w (unscaled)

// ======================= helpers =======================
__device__ __forceinline__ uint32_t smem_u32(const void* p) {
    uint32_t a;
    asm("{ .reg .u64 t; cvta.to.shared.u64 t, %1; cvt.u32.u64 %0, t; }" : "=r"(a) : "l"(p));
    return a;
}
__device__ __forceinline__ void cp16(uint32_t dst, const void* src) {
    asm volatile("cp.async.cg.shared.global [%0], [%1], 16;" :: "r"(dst), "l"(src));
}
__device__ __forceinline__ void cp_commit() {
    asm volatile("cp.async.commit_group;" ::: "memory");
}
__device__ __forceinline__ void ldsm4(uint32_t* r, uint32_t addr) {
    asm volatile("ldmatrix.sync.aligned.m8n8.x4.shared.b16 {%0,%1,%2,%3}, [%4];"
                 : "=r"(r[0]), "=r"(r[1]), "=r"(r[2]), "=r"(r[3]) : "r"(addr));
}
__device__ __forceinline__ void mma16816(float* d, const uint32_t* a,
                                         uint32_t b0, uint32_t b1) {
    asm volatile(
        "mma.sync.aligned.m16n8k16.row.col.f32.f16.f16.f32 "
        "{%0,%1,%2,%3}, {%4,%5,%6,%7}, {%8,%9}, {%0,%1,%2,%3};"
        : "+f"(d[0]), "+f"(d[1]), "+f"(d[2]), "+f"(d[3])
        : "r"(a[0]), "r"(a[1]), "r"(a[2]), "r"(a[3]), "r"(b0), "r"(b1));
}
__device__ __forceinline__ uint32_t pkh(__half a, __half b) {
    __half2 t(a, b);
    return *reinterpret_cast<uint32_t*>(&t);
}

// ======================= tiny prepass: rearrange + convert weight =======================
__global__ __launch_bounds__(256)
void prep_b(const float* __restrict__ w) {
    const int idx = blockIdx.x * 256 + threadIdx.x;   // < 49152
    const int col = idx & 127;       // n*4+x
    const int row = idx >> 7;
    const int c = row & 127;         // m*4+d
    const int k = row >> 7;
    const int n = col >> 2, xx = col & 3;
    const int m = c >> 2, d = c & 3;
    g_B[idx] = __float2half_rn(w[(((k * NIN + n) * 4 + xx) * 4 + d) * MMO + m]);
}

// ======================= main kernel =======================
__global__ __launch_bounds__(THREADS, 2)
void caps_mma_kernel(const float* __restrict__ x,
                     const float* __restrict__ gamma,
                     const float* __restrict__ beta,
                     float* __restrict__ out) {
    extern __shared__ char dsm[];
    const uint32_t smem = smem_u32(dsm);

    const int tid = threadIdx.x;
    const int wid = tid >> 5, lid = tid & 31;
    const int b  = blockIdx.y;
    const int w0 = blockIdx.x * WTILE;

    const int wm = wid & 1;           // rows wm*64 .. +64
    const int wn = wid >> 1;          // cols wn*64 .. +64
    const uint32_t lane_off = (uint32_t)((lid & 15) * ASTRIDE + (lid >> 4) * 16);

    const float* xb = x + (size_t)b * NIN * LLEN * 16;

    // ---- issue B[0] into buf0 (2048 cp16, 16/thread) ----
#pragma unroll
    for (int j = 0; j < 16; ++j) {
        const int u = tid + THREADS * j;
        const int row = u >> 4, seg = u & 15;
        cp16(smem + OFF_B + (uint32_t)(row * ASTRIDE + seg * 16),
             g_B + (size_t)row * 128 + seg * 8);
    }
    cp_commit();   // group 0: B0

    // ---- issue B[1] into buf1 ----
#pragma unroll
    for (int j = 0; j < 16; ++j) {
        const int u = tid + THREADS * j;
        const int row = u >> 4, seg = u & 15;
        cp16(smem + OFF_B + B_MAT + (uint32_t)(row * ASTRIDE + seg * 16),
             g_B + (size_t)(128 + row) * 128 + seg * 8);
    }
    cp_commit();   // group 1: B1

    // ---- build A tile inline: LDG fp32 -> f2h -> STS (overlaps B cp.async) ----
    // Part 1: ll in [0,32): no clamp (w0+31 <= 2047). 4096 float4, 32/thread.
#pragma unroll
    for (int j = 0; j < 32; ++j) {
        const int F  = tid + THREADS * j;
        const int a  = F & 3;
        const int ll = (F >> 2) & 31;
        const int nl = F >> 7;
        const float4 v = *reinterpret_cast<const float4*>(
            xb + ((size_t)nl * LLEN + (w0 + ll)) * 16 + a * 4);
        *reinterpret_cast<uint2*>(dsm + (uint32_t)((ll * 4 + a) * ASTRIDE + nl * 8)) =
            make_uint2(pkh(__float2half_rn(v.x), __float2half_rn(v.y)),
                       pkh(__float2half_rn(v.z), __float2half_rn(v.w)));
    }
    // Part 2: ll in {32,33} (overhang; clamp; garbage only for w>=WOUT, never stored)
#pragma unroll
    for (int j = 0; j < 2; ++j) {
        const int F  = tid + THREADS * j;   // < 256
        const int a  = F & 3;
        const int ll = 32 + ((F >> 2) & 1);
        const int nl = F >> 3;
        int l = w0 + ll; if (l > LLEN - 1) l = LLEN - 1;
        const float4 v = *reinterpret_cast<const float4*>(
            xb + ((size_t)nl * LLEN + l) * 16 + a * 4);
        *reinterpret_cast<uint2*>(dsm + (uint32_t)((ll * 4 + a) * ASTRIDE + nl * 8)) =
            make_uint2(pkh(__float2half_rn(v.x), __float2half_rn(v.y)),
                       pkh(__float2half_rn(v.z), __float2half_rn(v.w)));
    }

    float d[4][8][4];
#pragma unroll
    for (int i = 0; i < 4; i++)
#pragma unroll
        for (int j = 0; j < 8; j++)
#pragma unroll
            for (int q = 0; q < 4; q++) d[i][j][q] = 0.0f;

    for (int k = 0; k < 3; ++k) {
        if (k == 0) {
            asm volatile("cp.async.wait_group 1;" ::: "memory");   // B0 ready
        } else if (k == 1) {
            __syncthreads();   // buf0 free
#pragma unroll
            for (int j = 0; j < 16; ++j) {
                const int u = tid + THREADS * j;
                const int row = u >> 4, seg = u & 15;
                cp16(smem + OFF_B + (uint32_t)(row * ASTRIDE + seg * 16),
                     g_B + (size_t)(256 + row) * 128 + seg * 8);
            }
            cp_commit();   // group 2: B2
            asm volatile("cp.async.wait_group 1;" ::: "memory");   // B1 ready
        } else {
            asm volatile("cp.async.wait_group 0;" ::: "memory");   // B2 ready
        }
        __syncthreads();   // B[k] visible (k==0: A STS too)

        const uint32_t sA = smem + (uint32_t)((wm * 64 + 4 * k) * ASTRIDE) + lane_off;
        const uint32_t sB = smem + OFF_B + (uint32_t)((k & 1) ? B_MAT : 0)
                          + (uint32_t)(wn * 64 * ASTRIDE) + lane_off;

#pragma unroll
        for (int ks = 0; ks < 8; ++ks) {
            const uint32_t kb = ks * 32;   // k16 step = 32 bytes
            uint32_t Ar[4][4], Br[4][4];
#pragma unroll
            for (int mf = 0; mf < 4; ++mf)
                ldsm4(Ar[mf], sA + (uint32_t)(mf * 16) * ASTRIDE + kb);
#pragma unroll
            for (int bg = 0; bg < 4; ++bg)
                ldsm4(Br[bg], sB + (uint32_t)(bg * 16) * ASTRIDE + kb);
#pragma unroll
            for (int mf = 0; mf < 4; ++mf)
#pragma unroll
                for (int bg = 0; bg < 4; ++bg) {
                    mma16816(d[mf][bg * 2],     Ar[mf], Br[bg][0], Br[bg][2]);
                    mma16816(d[mf][bg * 2 + 1], Ar[mf], Br[bg][1], Br[bg][3]);
                }
        }
    }

    // ---- epilogue: accum -> smem, scale 1/32, fused LayerNorm over (a,d)=16 ----
    __syncthreads();
    float* S = reinterpret_cast<float*>(dsm);   // [128][SSTRIDE] = 67.6KB < SMEM_BYTES
    const int g = lid >> 2, t4 = lid & 3;
#pragma unroll
    for (int mf = 0; mf < 4; ++mf)
#pragma unroll
        for (int ng = 0; ng < 8; ++ng) {
            const int r = wm * 64 + mf * 16 + g;
            const int c = wn * 64 + ng * 8 + t4 * 2;
            S[r * SSTRIDE + c]           = d[mf][ng][0];
            S[r * SSTRIDE + c + 1]       = d[mf][ng][1];
            S[(r + 8) * SSTRIDE + c]     = d[mf][ng][2];
            S[(r + 8) * SSTRIDE + c + 1] = d[mf][ng][3];
        }
    __syncthreads();

    float gam[16], bet[16];
#pragma unroll
    for (int i = 0; i < 16; i++) { gam[i] = __ldg(gamma + i); bet[i] = __ldg(beta + i); }

    // 1024 LN groups (wl 0..31 x m 0..31), 8 per thread
#pragma unroll
    for (int gq = 0; gq < 8; ++gq) {
        const int G  = tid + gq * THREADS;
        const int wl = G >> 5;
        const int m  = G & 31;
        const int w  = w0 + wl;
        if (w >= WOUTN) continue;

        float vals[16];
#pragma unroll
        for (int a = 0; a < 4; a++) {
            const float4 v = *reinterpret_cast<const float4*>(
                S + (wl * 4 + a) * SSTRIDE + m * 4);
            vals[a * 4 + 0] = v.x * OUT_SCALE; vals[a * 4 + 1] = v.y * OUT_SCALE;
            vals[a * 4 + 2] = v.z * OUT_SCALE; vals[a * 4 + 3] = v.w * OUT_SCALE;
        }
        float mu = 0.0f;
#pragma unroll
        for (int i = 0; i < 16; i++) mu += vals[i];
        mu *= 0.0625f;
        float var = 0.0f;
#pragma unroll
        for (int i = 0; i < 16; i++) {
            const float dv = vals[i] - mu;
            var = fmaf(dv, dv, var);
        }
        var *= 0.0625f;
        const float inv = rsqrtf(var + 1e-5f);

        const size_t base = (((size_t)b * MMO + m) * WOUTN + w) * 16;
#pragma unroll
        for (int q = 0; q < 4; q++) {
            float4 o;
            o.x = fmaf((vals[q * 4 + 0] - mu) * inv, gam[q * 4 + 0], bet[q * 4 + 0]);
            o.y = fmaf((vals[q * 4 + 1] - mu) * inv, gam[q * 4 + 1], bet[q * 4 + 1]);
            o.z = fmaf((vals[q * 4 + 2] - mu) * inv, gam[q * 4 + 2], bet[q * 4 + 2]);
            o.w = fmaf((vals[q * 4 + 3] - mu) * inv, gam[q * 4 + 3], bet[q * 4 + 3]);
            *reinterpret_cast<float4*>(out + base + q * 4) = o;
        }
    }
}

extern "C" void kernel_launch(void* const* d_in, const int* in_sizes, int n_in,
                              void* d_out, int out_size) {
    const float* x     = (const float*)d_in[0];
    const float* w     = (const float*)d_in[1];
    const float* gamma = (const float*)d_in[2];
    const float* beta  = (const float*)d_in[3];
    float* out = (float*)d_out;

    prep_b<<<192, 256>>>(w);

    cudaFuncSetAttribute(caps_mma_kernel,
                         cudaFuncAttributeMaxDynamicSharedMemorySize, SMEM_BYTES);
    dim3 grid(64, BB);   // 64 w-tiles x 16 batches
    caps_mma_kernel<<<grid, THREADS, SMEM_BYTES>>>(x, gamma, beta, out);
}

// round 11
// speedup vs baseline: 1.1577x; 1.0523x over previous
#include <cuda_runtime.h>
#include <cuda_fp16.h>
#include <cstdint>

// CapsuleConv = GEMM (rows=(b,w,a)=130944, K=(k,n,x)=384, cols=(m,d)=128) + fused LayerNorm.
// Single-pass fp16 mma.sync (R7 structure), overhead-reduced:
//  - A-build: paired LDG.128 -> one STS.128 (halved store instructions)
//  - epilogue: single CTA barrier, then warp-local staging + LN (no cross-warp deps)
//  - incremented LDSM address registers in the mainloop

#define BB    16
#define NIN   32
#define LLEN  2048
#define MMO   32
#define WOUTN 2046

#define THREADS 256
#define WTILE   32          // w per CTA (M = 128 output rows)
#define ASTRIDE 272         // smem row stride bytes (128 fp16 = 256B + 16 pad)
#define A_ROWS  136         // (WTILE + 2) * 4
#define A_MAT   (A_ROWS * ASTRIDE)        // 36992
#define B_MAT   (128 * ASTRIDE)           // 34816
#define OFF_B   A_MAT
#define SMEM_BYTES (A_MAT + 2 * B_MAT)    // 106624 -> 2 CTAs/SM
#define WSTRIDE 68          // warp-local epilogue scratch stride (floats)
#define OUT_SCALE (1.0f / 32.0f)

// ---- persistent scratch: rearranged fp16 weight ----
__device__ __half g_B[3 * 128 * 128];     // B[k][c=m*4+d][n*4+x] = w (unscaled)

// ======================= helpers =======================
__device__ __forceinline__ uint32_t smem_u32(const void* p) {
    uint32_t a;
    asm("{ .reg .u64 t; cvta.to.shared.u64 t, %1; cvt.u32.u64 %0, t; }" : "=r"(a) : "l"(p));
    return a;
}
__device__ __forceinline__ void cp16(uint32_t dst, const void* src) {
    asm volatile("cp.async.cg.shared.global [%0], [%1], 16;" :: "r"(dst), "l"(src));
}
__device__ __forceinline__ void cp_commit() {
    asm volatile("cp.async.commit_group;" ::: "memory");
}
__device__ __forceinline__ void ldsm4(uint32_t* r, uint32_t addr) {
    asm volatile("ldmatrix.sync.aligned.m8n8.x4.shared.b16 {%0,%1,%2,%3}, [%4];"
                 : "=r"(r[0]), "=r"(r[1]), "=r"(r[2]), "=r"(r[3]) : "r"(addr));
}
__device__ __forceinline__ void mma16816(float* d, const uint32_t* a,
                                         uint32_t b0, uint32_t b1) {
    asm volatile(
        "mma.sync.aligned.m16n8k16.row.col.f32.f16.f16.f32 "
        "{%0,%1,%2,%3}, {%4,%5,%6,%7}, {%8,%9}, {%0,%1,%2,%3};"
        : "+f"(d[0]), "+f"(d[1]), "+f"(d[2]), "+f"(d[3])
        : "r"(a[0]), "r"(a[1]), "r"(a[2]), "r"(a[3]), "r"(b0), "r"(b1));
}
__device__ __forceinline__ uint32_t pkh(__half a, __half b) {
    __half2 t(a, b);
    return *reinterpret_cast<uint32_t*>(&t);
}

// ======================= tiny prepass: rearrange + convert weight =======================
__global__ __launch_bounds__(256)
void prep_b(const float* __restrict__ w) {
    const int idx = blockIdx.x * 256 + threadIdx.x;   // < 49152
    const int col = idx & 127;       // n*4+x
    const int row = idx >> 7;
    const int c = row & 127;         // m*4+d
    const int k = row >> 7;
    const int n = col >> 2, xx = col & 3;
    const int m = c >> 2, d = c & 3;
    g_B[idx] = __float2half_rn(w[(((k * NIN + n) * 4 + xx) * 4 + d) * MMO + m]);
}

// ======================= main kernel =======================
__global__ __launch_bounds__(THREADS, 2)
void caps_mma_kernel(const float* __restrict__ x,
                     const float* __restrict__ gamma,
                     const float* __restrict__ beta,
                     float* __restrict__ out) {
    extern __shared__ char dsm[];
    const uint32_t smem = smem_u32(dsm);

    const int tid = threadIdx.x;
    const int wid = tid >> 5, lid = tid & 31;
    const int b  = blockIdx.y;
    const int w0 = blockIdx.x * WTILE;

    const int wm = wid & 3;           // rows wm*32 .. +32
    const int wn = wid >> 2;          // cols wn*64 .. +64
    const uint32_t lane_off = (uint32_t)((lid & 15) * ASTRIDE + (lid >> 4) * 16);

    const float* xb = x + (size_t)b * NIN * LLEN * 16;

    // ---- issue B[0] into buf0 (2048 cp16, 8/thread) ----
#pragma unroll
    for (int j = 0; j < 8; ++j) {
        const int u = tid + THREADS * j;
        const int row = u >> 4, seg = u & 15;
        cp16(smem + OFF_B + (uint32_t)(row * ASTRIDE + seg * 16),
             g_B + (size_t)row * 128 + seg * 8);
    }
    cp_commit();   // group 0: B0

    // ---- issue B[1] into buf1 ----
#pragma unroll
    for (int j = 0; j < 8; ++j) {
        const int u = tid + THREADS * j;
        const int row = u >> 4, seg = u & 15;
        cp16(smem + OFF_B + B_MAT + (uint32_t)(row * ASTRIDE + seg * 16),
             g_B + (size_t)(128 + row) * 128 + seg * 8);
    }
    cp_commit();   // group 1: B1

    // ---- build A tile inline: paired LDG.128 fp32 -> f2h -> one STS.128 ----
    // pair P -> (a, ll, s): sources nl = 2s, 2s+1 (same row), dst 16B at row*ASTRIDE + s*16.
    // Lane runs cover 512B contiguous in x; STS.128 tiles all 32 banks (272B stride).
    // Part 1: ll in [0,32): no clamp (w0+31 <= 2047). 2048 pairs, 8/thread.
#pragma unroll
    for (int j = 0; j < 8; ++j) {
        const int P  = tid + THREADS * j;
        const int a  = P & 3;
        const int ll = (P >> 2) & 31;
        const int s  = P >> 7;            // 0..15
        const float* base = xb + ((size_t)(2 * s) * LLEN + (w0 + ll)) * 16 + a * 4;
        const float4 v0 = *reinterpret_cast<const float4*>(base);
        const float4 v1 = *reinterpret_cast<const float4*>(base + (size_t)LLEN * 16);
        *reinterpret_cast<uint4*>(dsm + (uint32_t)((ll * 4 + a) * ASTRIDE + s * 16)) =
            make_uint4(pkh(__float2half_rn(v0.x), __float2half_rn(v0.y)),
                       pkh(__float2half_rn(v0.z), __float2half_rn(v0.w)),
                       pkh(__float2half_rn(v1.x), __float2half_rn(v1.y)),
                       pkh(__float2half_rn(v1.z), __float2half_rn(v1.w)));
    }
    // Part 2: ll in {32,33} (overhang; clamp; garbage only for w>=WOUT, never stored)
    if (tid < 128) {
        const int a  = tid & 3;
        const int ll = 32 + ((tid >> 2) & 1);
        const int s  = tid >> 3;          // 0..15
        int l = w0 + ll; if (l > LLEN - 1) l = LLEN - 1;
        const float* base = xb + ((size_t)(2 * s) * LLEN + l) * 16 + a * 4;
        const float4 v0 = *reinterpret_cast<const float4*>(base);
        const float4 v1 = *reinterpret_cast<const float4*>(base + (size_t)LLEN * 16);
        *reinterpret_cast<uint4*>(dsm + (uint32_t)((ll * 4 + a) * ASTRIDE + s * 16)) =
            make_uint4(pkh(__float2half_rn(v0.x), __float2half_rn(v0.y)),
                       pkh(__float2half_rn(v0.z), __float2half_rn(v0.w)),
                       pkh(__float2half_rn(v1.x), __float2half_rn(v1.y)),
                       pkh(__float2half_rn(v1.z), __float2half_rn(v1.w)));
    }

    float d[2][8][4];
#pragma unroll
    for (int i = 0; i < 2; i++)
#pragma unroll
        for (int j = 0; j < 8; j++)
#pragma unroll
            for (int q = 0; q < 4; q++) d[i][j][q] = 0.0f;

    for (int k = 0; k < 3; ++k) {
        if (k == 0) {
            asm volatile("cp.async.wait_group 1;" ::: "memory");   // B0 ready
        } else if (k == 1) {
            __syncthreads();   // buf0 free
#pragma unroll
            for (int j = 0; j < 8; ++j) {
                const int u = tid + THREADS * j;
                const int row = u >> 4, seg = u & 15;
                cp16(smem + OFF_B + (uint32_t)(row * ASTRIDE + seg * 16),
                     g_B + (size_t)(256 + row) * 128 + seg * 8);
            }
            cp_commit();   // group 2: B2
            asm volatile("cp.async.wait_group 1;" ::: "memory");   // B1 ready
        } else {
            asm volatile("cp.async.wait_group 0;" ::: "memory");   // B2 ready
        }
        __syncthreads();   // B[k] visible (k==0: A STS too)

        // incremented LDSM address registers (+32B per k16 step)
        uint32_t aA0 = smem + (uint32_t)((wm * 32 + 4 * k) * ASTRIDE) + lane_off;
        uint32_t aA1 = aA0 + 16 * ASTRIDE;
        uint32_t aB0 = smem + OFF_B + (uint32_t)((k & 1) ? B_MAT : 0)
                     + (uint32_t)(wn * 64 * ASTRIDE) + lane_off;
        uint32_t aB1 = aB0 + 16 * ASTRIDE;
        uint32_t aB2 = aB0 + 32 * ASTRIDE;
        uint32_t aB3 = aB0 + 48 * ASTRIDE;

#pragma unroll
        for (int ks = 0; ks < 8; ++ks) {
            uint32_t Ar[2][4], Br[4][4];
            ldsm4(Ar[0], aA0); ldsm4(Ar[1], aA1);
            ldsm4(Br[0], aB0); ldsm4(Br[1], aB1);
            ldsm4(Br[2], aB2); ldsm4(Br[3], aB3);
            aA0 += 32; aA1 += 32; aB0 += 32; aB1 += 32; aB2 += 32; aB3 += 32;
#pragma unroll
            for (int mf = 0; mf < 2; ++mf)
#pragma unroll
                for (int bg = 0; bg < 4; ++bg) {
                    mma16816(d[mf][bg * 2],     Ar[mf], Br[bg][0], Br[bg][2]);
                    mma16816(d[mf][bg * 2 + 1], Ar[mf], Br[bg][1], Br[bg][3]);
                }
        }
    }

    // ---- epilogue: ONE barrier, then fully warp-local staging + LayerNorm ----
    __syncthreads();   // all LDSM reads of A/B done; smem reusable as scratch
    float* Sw = reinterpret_cast<float*>(dsm) + wid * (32 * WSTRIDE);   // 8.7KB/warp
    const int g = lid >> 2, t4 = lid & 3;
#pragma unroll
    for (int mf = 0; mf < 2; ++mf)
#pragma unroll
        for (int ng = 0; ng < 8; ++ng) {
            const int r = mf * 16 + g;               // warp-local row 0..31
            const int c = ng * 8 + t4 * 2;           // warp-local col 0..63
            Sw[r * WSTRIDE + c]           = d[mf][ng][0];
            Sw[r * WSTRIDE + c + 1]       = d[mf][ng][1];
            Sw[(r + 8) * WSTRIDE + c]     = d[mf][ng][2];
            Sw[(r + 8) * WSTRIDE + c + 1] = d[mf][ng][3];
        }
    __syncwarp();

    float gam[16], bet[16];
#pragma unroll
    for (int i = 0; i < 16; i++) { gam[i] = __ldg(gamma + i); bet[i] = __ldg(beta + i); }

    // 128 LN groups per warp (8 wl x 16 m), 4 per lane
#pragma unroll
    for (int q = 0; q < 4; ++q) {
        const int G  = lid + 32 * q;                 // 0..127
        const int wl = G >> 4;                       // warp-local 0..7
        const int ml = G & 15;                       // warp-local 0..15
        const int w  = w0 + wm * 8 + wl;
        const int m  = wn * 16 + ml;
        if (w >= WOUTN) continue;

        float vals[16];
#pragma unroll
        for (int a = 0; a < 4; a++) {
            const float4 v = *reinterpret_cast<const float4*>(
                Sw + (wl * 4 + a) * WSTRIDE + ml * 4);
            vals[a * 4 + 0] = v.x * OUT_SCALE; vals[a * 4 + 1] = v.y * OUT_SCALE;
            vals[a * 4 + 2] = v.z * OUT_SCALE; vals[a * 4 + 3] = v.w * OUT_SCALE;
        }
        float mu = 0.0f;
#pragma unroll
        for (int i = 0; i < 16; i++) mu += vals[i];
        mu *= 0.0625f;
        float var = 0.0f;
#pragma unroll
        for (int i = 0; i < 16; i++) {
            const float dv = vals[i] - mu;
            var = fmaf(dv, dv, var);
        }
        var *= 0.0625f;
        const float inv = rsqrtf(var + 1e-5f);

        const size_t base = (((size_t)b * MMO + m) * WOUTN + w) * 16;
#pragma unroll
        for (int p = 0; p < 4; p++) {
            float4 o;
            o.x = fmaf((vals[p * 4 + 0] - mu) * inv, gam[p * 4 + 0], bet[p * 4 + 0]);
            o.y = fmaf((vals[p * 4 + 1] - mu) * inv, gam[p * 4 + 1], bet[p * 4 + 1]);
            o.z = fmaf((vals[p * 4 + 2] - mu) * inv, gam[p * 4 + 2], bet[p * 4 + 2]);
            o.w = fmaf((vals[p * 4 + 3] - mu) * inv, gam[p * 4 + 3], bet[p * 4 + 3]);
            *reinterpret_cast<float4*>(out + base + p * 4) = o;
        }
    }
}

extern "C" void kernel_launch(void* const* d_in, const int* in_sizes, int n_in,
                              void* d_out, int out_size) {
    const float* x     = (const float*)d_in[0];
    const float* w     = (const float*)d_in[1];
    const float* gamma = (const float*)d_in[2];
    const float* beta  = (const float*)d_in[3];
    float* out = (float*)d_out;

    prep_b<<<192, 256>>>(w);

    cudaFuncSetAttribute(caps_mma_kernel,
                         cudaFuncAttributeMaxDynamicSharedMemorySize, SMEM_BYTES);
    dim3 grid(64, BB);   // 64 w-tiles x 16 batches
    caps_mma_kernel<<<grid, THREADS, SMEM_BYTES>>>(x, gamma, beta, out);
}